// round 11
// baseline (speedup 1.0000x reference)
#include <cuda_runtime.h>
#include <cuda_fp16.h>
#include <cstdint>

#define BATCH 4
#define SEQ   2048
#define EDIM  1024
#define QN    4
#define HN    16
#define DH    64
#define NTOK  (BATCH*SEQ)        // 8192
#define QCOLS (QN*EDIM)          // 4096
#define NQKV  (QCOLS + 2*EDIM)   // 6144

// ------------------------- scratch (static, no runtime alloc) ---------------
__device__ __half g_qkv[(size_t)NTOK * NQKV];
__device__ __half g_xf[(size_t)NTOK * EDIM];
__device__ __half g_y[(size_t)NTOK * EDIM];
__device__ __half g_wqkv[(size_t)NQKV * EDIM];
__device__ __half g_wo[(size_t)EDIM * EDIM];

// ------------------------- helpers ------------------------------------------
__device__ __forceinline__ uint32_t smem_to_u32(const void* p) {
    uint32_t a;
    asm("{ .reg .u64 t; cvta.to.shared.u64 t, %1; cvt.u32.u64 %0, t; }" : "=r"(a) : "l"(p));
    return a;
}
__device__ __forceinline__ void cp16(uint32_t dst, const void* src) {
    asm volatile("cp.async.cg.shared.global [%0], [%1], 16;" :: "r"(dst), "l"(src));
}
__device__ __forceinline__ void cp_commit() { asm volatile("cp.async.commit_group;" ::: "memory"); }
__device__ __forceinline__ void cp_wait0()  { asm volatile("cp.async.wait_group 0;"  ::: "memory"); }
__device__ __forceinline__ void cp_wait1()  { asm volatile("cp.async.wait_group 1;"  ::: "memory"); }
__device__ __forceinline__ void ldx4(uint32_t* r, uint32_t addr) {
    asm volatile("ldmatrix.sync.aligned.m8n8.x4.shared.b16 {%0,%1,%2,%3}, [%4];"
        : "=r"(r[0]), "=r"(r[1]), "=r"(r[2]), "=r"(r[3]) : "r"(addr));
}
__device__ __forceinline__ void mma16816(float* d, const uint32_t* a, const uint32_t* b) {
    asm volatile("mma.sync.aligned.m16n8k16.row.col.f32.f16.f16.f32 "
        "{%0,%1,%2,%3}, {%4,%5,%6,%7}, {%8,%9}, {%0,%1,%2,%3};"
        : "+f"(d[0]), "+f"(d[1]), "+f"(d[2]), "+f"(d[3])
        : "r"(a[0]), "r"(a[1]), "r"(a[2]), "r"(a[3]), "r"(b[0]), "r"(b[1]));
}

// ------------------------- fused conversion ---------------------------------
#define S_X   2097152
#define S_WQ  (S_X  + 1048576)
#define S_WK  (S_WQ + 262144)
#define S_WV  (S_WK + 262144)
#define S_ALL (S_WV + 262144)

__device__ __forceinline__ uint2 f4_to_h4(float4 v) {
    __half2 h[2];
    h[0] = __floats2half2_rn(v.x, v.y);
    h[1] = __floats2half2_rn(v.z, v.w);
    return *(uint2*)h;
}

__global__ void __launch_bounds__(256)
conv_all(const float* __restrict__ x, const float* __restrict__ Wq,
         const float* __restrict__ Wk, const float* __restrict__ Wv,
         const float* __restrict__ Wo, __half* __restrict__ xf,
         __half* __restrict__ wqkv, __half* __restrict__ wo)
{
    int i = blockIdx.x * 256 + threadIdx.x;
    if (i >= S_ALL) return;
    const float4* src; uint2* dst; int j;
    if (i < S_X)       { src = (const float4*)x;  dst = (uint2*)xf;   j = i; }
    else if (i < S_WQ) { src = (const float4*)Wq; dst = (uint2*)wqkv; j = i - S_X; }
    else if (i < S_WK) { src = (const float4*)Wk; dst = (uint2*)wqkv + 1048576; j = i - S_WQ; }
    else if (i < S_WV) { src = (const float4*)Wv; dst = (uint2*)wqkv + 1310720; j = i - S_WK; }
    else               { src = (const float4*)Wo; dst = (uint2*)wo;   j = i - S_WV; }
    dst[j] = f4_to_h4(src[j]);
}

// ------------------------- HMMA fp16 GEMM -----------------------------------
// C[m,n] = sum_k A[m,k]*W[n,k] + bias[n].
// Template MB: CTA tile = (128*MB) x 128, MB*128 threads (MB*4 warps,
// warp grid (2*MB) in M x 2 in N, warp tile 64x64).
// BK=64, 3-stage cp.async, XOR-swizzled 128B rows.
#define GBK    64
#define TILEWB 16384                         // W tile: 128x64 halfs
#define NSTG   3

template <int MB, typename OutT>
__global__ void __launch_bounds__(MB * 128, MB == 1 ? 2 : 1)
gemm_f16(const __half* __restrict__ A, const __half* __restrict__ W,
         const float* __restrict__ bias0, const float* __restrict__ bias1,
         const float* __restrict__ bias2, int nb1, int nb2,
         OutT* __restrict__ C, int N, int K)
{
    constexpr int TILEA  = MB * 128 * 128;   // A tile bytes
    constexpr int STAGEB = TILEA + TILEWB;
    extern __shared__ __align__(16) char smem[];
    const uint32_t sb = smem_to_u32(smem);
    const int tid = threadIdx.x;
    const int lane = tid & 31;
    const int warp = tid >> 5;
    const int bm = blockIdx.y * (MB * 128);
    const int bn = blockIdx.x * 128;
    const int wm0 = (warp & (2 * MB - 1)) * 64;
    const int wn0 = (warp / (2 * MB)) * 64;

    float acc[4][8][4];
#pragma unroll
    for (int i = 0; i < 4; i++)
#pragma unroll
        for (int j = 0; j < 8; j++)
#pragma unroll
            for (int r = 0; r < 4; r++) acc[i][j][r] = 0.f;

    const int lrow = tid >> 3;     // 0..16*MB-1
    const int lq   = tid & 7;

    auto load_chunk = [&](int stage, int ck) {
        const uint32_t stb = sb + stage * STAGEB;
        const size_t kof = (size_t)ck * GBK + lq * 8;
#pragma unroll
        for (int l = 0; l < 8; l++) {
            int row = lrow + l * (16 * MB);
            uint32_t dst = stb + row * 128 + ((lq ^ (row & 7)) << 4);
            cp16(dst, A + (size_t)(bm + row) * K + kof);
        }
#pragma unroll
        for (int l = 0; l < 8 / MB; l++) {
            int row = lrow + l * (16 * MB);
            uint32_t dst = stb + TILEA + row * 128 + ((lq ^ (row & 7)) << 4);
            cp16(dst, W + (size_t)(bn + row) * K + kof);
        }
    };

    const int arow[4] = {wm0 + 0 * 16 + (lane & 15), wm0 + 1 * 16 + (lane & 15),
                         wm0 + 2 * 16 + (lane & 15), wm0 + 3 * 16 + (lane & 15)};
    const int ahalf = lane >> 4;
    const int brow[4] = {wn0 + 0 * 16 + (lane & 7) + ((lane >> 4) << 3),
                         wn0 + 1 * 16 + (lane & 7) + ((lane >> 4) << 3),
                         wn0 + 2 * 16 + (lane & 7) + ((lane >> 4) << 3),
                         wn0 + 3 * 16 + (lane & 7) + ((lane >> 4) << 3)};
    const int bhalf = (lane >> 3) & 1;

    auto compute = [&](int stage) {
        const uint32_t tA = sb + stage * STAGEB;
        const uint32_t tW = tA + TILEA;
#pragma unroll
        for (int ks = 0; ks < 4; ks++) {
            uint32_t a[4][4], b[4][4];
#pragma unroll
            for (int rb = 0; rb < 4; rb++) {
                int r = arow[rb];
                uint32_t q = (uint32_t)((2 * ks + ahalf) ^ (r & 7));
                ldx4(a[rb], tA + (uint32_t)r * 128 + (q << 4));
            }
#pragma unroll
            for (int hb = 0; hb < 4; hb++) {
                int r = brow[hb];
                uint32_t q = (uint32_t)((2 * ks + bhalf) ^ (r & 7));
                ldx4(b[hb], tW + (uint32_t)r * 128 + (q << 4));
            }
#pragma unroll
            for (int rb = 0; rb < 4; rb++) {
#pragma unroll
                for (int nb = 0; nb < 8; nb++) {
                    mma16816(acc[rb][nb], a[rb], &b[nb >> 1][(nb & 1) * 2]);
                }
            }
        }
    };

    const int nchunk = K / GBK;   // 16
    load_chunk(0, 0); cp_commit();
    load_chunk(1, 1); cp_commit();
    for (int c = 0; c < nchunk; c++) {
        if (c == nchunk - 1) cp_wait0(); else cp_wait1();
        __syncthreads();
        if (c + 2 < nchunk) { load_chunk((c + 2) % NSTG, c + 2); cp_commit(); }
        compute(c % NSTG);
    }

    const float* bp; int segbase;
    if (bn < nb1)      { bp = bias0; segbase = 0;   }
    else if (bn < nb2) { bp = bias1; segbase = nb1; }
    else               { bp = bias2; segbase = nb2; }

#pragma unroll
    for (int rb = 0; rb < 4; rb++) {
#pragma unroll
        for (int nb = 0; nb < 8; nb++) {
            int row = bm + wm0 + rb * 16 + (lane >> 2);
            int col = bn + wn0 + nb * 8 + (lane & 3) * 2;
            float b0 = bp[col - segbase], b1 = bp[col - segbase + 1];
            float o0 = acc[rb][nb][0] + b0, o1 = acc[rb][nb][1] + b1;
            float o2 = acc[rb][nb][2] + b0, o3 = acc[rb][nb][3] + b1;
            if constexpr (sizeof(OutT) == 2) {
                __half2 h0 = __floats2half2_rn(o0, o1);
                __half2 h1 = __floats2half2_rn(o2, o3);
                *(__half2*)((__half*)C + (size_t)row * N + col)       = h0;
                *(__half2*)((__half*)C + (size_t)(row + 8) * N + col) = h1;
            } else {
                float2 v0 = {o0, o1}, v1 = {o2, o3};
                *(float2*)((float*)C + (size_t)row * N + col)       = v0;
                *(float2*)((float*)C + (size_t)(row + 8) * N + col) = v1;
            }
        }
    }
}

// ------------------------- per-token head-mixing attention ------------------
#define KSTR 68
__global__ void __launch_bounds__(256)
attn_kernel(const __half* __restrict__ gqkv, __half* __restrict__ gy)
{
    const int tok = blockIdx.x;
    const int t = threadIdx.x;
    const __half* base = gqkv + (size_t)tok * NQKV;

    __shared__ __align__(16) float qs[QN * HN * DH];
    __shared__ __align__(16) float ks[HN * KSTR];
    __shared__ __align__(16) float vs[HN * DH];
    __shared__ float sc[QN][HN][HN];
    __shared__ float ps[HN][HN];

    {
        const uint4* qg = (const uint4*)base;
#pragma unroll
        for (int l = 0; l < 2; l++) {
            uint4 p = qg[t + l * 256];
            const __half2* hp = (const __half2*)&p;
            float* dst = qs + (t + l * 256) * 8;
#pragma unroll
            for (int j = 0; j < 4; j++) {
                float2 f = __half22float2(hp[j]);
                dst[2 * j] = f.x; dst[2 * j + 1] = f.y;
            }
        }
    }
    if (t < 128) {
        uint4 p = ((const uint4*)(base + QCOLS))[t];
        const __half2* hp = (const __half2*)&p;
        int g = t >> 3, d = (t * 8) & 63;
        float* kr = ks + g * KSTR + d;
#pragma unroll
        for (int j = 0; j < 4; j++) {
            float2 f = __half22float2(hp[j]);
            kr[2 * j] = f.x; kr[2 * j + 1] = f.y;
        }
    } else {
        int tt = t - 128;
        uint4 p = ((const uint4*)(base + QCOLS + EDIM))[tt];
        const __half2* hp = (const __half2*)&p;
        int g = tt >> 3, d = (tt * 8) & 63;
        float* vr = vs + g * DH + d;
#pragma unroll
        for (int j = 0; j < 4; j++) {
            float2 f = __half22float2(hp[j]);
            vr[2 * j] = f.x; vr[2 * j + 1] = f.y;
        }
    }
    __syncthreads();

    const float scale = 0.125f;
#pragma unroll
    for (int l = 0; l < 4; l++) {
        int e = t + l * 256;
        int qq = e >> 8, h = (e >> 4) & 15, g = e & 15;
        const float4* qp4 = (const float4*)(qs + (qq * HN + h) * DH);
        const float4* kp4 = (const float4*)(ks + g * KSTR);
        float s_ = 0.f;
#pragma unroll
        for (int d = 0; d < 16; d++) {
            float4 a = qp4[d], b = kp4[d];
            s_ += a.x * b.x + a.y * b.y + a.z * b.z + a.w * b.w;
        }
        sc[qq][h][g] = s_ * scale;
    }
    __syncthreads();

    if (t < 64) {
        int qq = t >> 4, h = t & 15;
        float* row = sc[qq][h];
        float m = row[0];
#pragma unroll
        for (int g = 1; g < 16; g++) m = fmaxf(m, row[g]);
        float ssum = 0.f;
#pragma unroll
        for (int g = 0; g < 16; g++) { float ex = __expf(row[g] - m); row[g] = ex; ssum += ex; }
        float inv = 1.f / ssum;
#pragma unroll
        for (int g = 0; g < 16; g++) row[g] *= inv;
    }
    __syncthreads();

    {
        int h = t >> 4, g = t & 15;
        ps[h][g] = sc[0][h][g] + sc[1][h][g] + sc[2][h][g] + sc[3][h][g];
    }
    __syncthreads();

    const int b = tok >> 11, s = tok & 2047;
    {
        int h = t >> 4;
        int d0 = (t * 4) & 63;
        const float4* vp4 = (const float4*)vs;
        float4 o = {0.f, 0.f, 0.f, 0.f};
#pragma unroll
        for (int g = 0; g < 16; g++) {
            float p = ps[h][g];
            float4 vv = vp4[g * 16 + (d0 >> 2)];
            o.x = fmaf(p, vv.x, o.x); o.y = fmaf(p, vv.y, o.y);
            o.z = fmaf(p, vv.z, o.z); o.w = fmaf(p, vv.w, o.w);
        }
        __half2 h0 = __floats2half2_rn(o.x, o.y);
        __half2 h1 = __floats2half2_rn(o.z, o.w);
        size_t oi = (((size_t)b * HN + h) * SEQ + s) * DH + d0;
        *(__half2*)(gy + oi)     = h0;
        *(__half2*)(gy + oi + 2) = h1;
    }
}

// ------------------------- launch -------------------------------------------
extern "C" void kernel_launch(void* const* d_in, const int* in_sizes, int n_in,
                              void* d_out, int out_size)
{
    const float* x  = (const float*)d_in[0];
    const float* Wq = (const float*)d_in[1];
    const float* bq = (const float*)d_in[2];
    const float* Wk = (const float*)d_in[3];
    const float* bk = (const float*)d_in[4];
    const float* Wv = (const float*)d_in[5];
    const float* bv = (const float*)d_in[6];
    const float* Wo = (const float*)d_in[7];
    const float* bo = (const float*)d_in[8];
    float* out = (float*)d_out;
    (void)in_sizes; (void)n_in; (void)out_size;

    __half *qkv, *xf, *gy, *wqkv, *wo;
    cudaGetSymbolAddress((void**)&qkv, g_qkv);
    cudaGetSymbolAddress((void**)&xf, g_xf);
    cudaGetSymbolAddress((void**)&gy, g_y);
    cudaGetSymbolAddress((void**)&wqkv, g_wqkv);
    cudaGetSymbolAddress((void**)&wo, g_wo);

    const int GSMEM2 = NSTG * (2 * 128 * 128 + TILEWB);   // 147456 (MB=2)
    const int GSMEM1 = NSTG * (128 * 128 + TILEWB);       // 98304  (MB=1)
    cudaFuncSetAttribute(gemm_f16<2, __half>, cudaFuncAttributeMaxDynamicSharedMemorySize, GSMEM2);
    cudaFuncSetAttribute(gemm_f16<1, float>,  cudaFuncAttributeMaxDynamicSharedMemorySize, GSMEM1);

    // 1) fused fp32 -> fp16 conversions
    conv_all<<<(S_ALL + 255) / 256, 256>>>(x, Wq, Wk, Wv, Wo, xf, wqkv, wo);

    // 2) fused QKV projection: 256x128 tiles, 1536 CTAs
    gemm_f16<2, __half><<<dim3(NQKV / 128, NTOK / 256), 256, GSMEM2>>>(
        xf, wqkv, bq, bk, bv, QCOLS, QCOLS + EDIM, qkv, NQKV, EDIM);

    // 3) per-token attention -> y fp16 ((B,H,S,D) flat == (B,S,E) flat)
    attn_kernel<<<NTOK, 256>>>(qkv, gy);

    // 4) output projection: 128x128 tiles, 512 CTAs (tail-friendly)
    gemm_f16<1, float><<<dim3(EDIM / 128, NTOK / 128), 128, GSMEM1>>>(
        gy, wo, bo, bo, bo, 1 << 30, 1 << 30, out, EDIM, EDIM);
}

// round 14
// speedup vs baseline: 1.0373x; 1.0373x over previous
#include <cuda_runtime.h>
#include <cuda_fp16.h>
#include <cstdint>

#define BATCH 4
#define SEQ   2048
#define EDIM  1024
#define QN    4
#define HN    16
#define DH    64
#define NTOK  (BATCH*SEQ)        // 8192
#define QCOLS (QN*EDIM)          // 4096
#define NQKV  (QCOLS + 2*EDIM)   // 6144

// ------------------------- scratch (static, no runtime alloc) ---------------
__device__ __half g_qkv[(size_t)NTOK * NQKV];
__device__ __half g_xf[(size_t)NTOK * EDIM];
__device__ __half g_y[(size_t)NTOK * EDIM];
__device__ __half g_wqkv[(size_t)NQKV * EDIM];
__device__ __half g_wo[(size_t)EDIM * EDIM];

// ------------------------- helpers ------------------------------------------
__device__ __forceinline__ uint32_t smem_to_u32(const void* p) {
    uint32_t a;
    asm("{ .reg .u64 t; cvta.to.shared.u64 t, %1; cvt.u32.u64 %0, t; }" : "=r"(a) : "l"(p));
    return a;
}
__device__ __forceinline__ void cp16(uint32_t dst, const void* src) {
    asm volatile("cp.async.cg.shared.global [%0], [%1], 16;" :: "r"(dst), "l"(src));
}
__device__ __forceinline__ void cp_commit() { asm volatile("cp.async.commit_group;" ::: "memory"); }
__device__ __forceinline__ void cp_wait0()  { asm volatile("cp.async.wait_group 0;"  ::: "memory"); }
__device__ __forceinline__ void cp_wait1()  { asm volatile("cp.async.wait_group 1;"  ::: "memory"); }
__device__ __forceinline__ void ldx4(uint32_t* r, uint32_t addr) {
    asm volatile("ldmatrix.sync.aligned.m8n8.x4.shared.b16 {%0,%1,%2,%3}, [%4];"
        : "=r"(r[0]), "=r"(r[1]), "=r"(r[2]), "=r"(r[3]) : "r"(addr));
}
__device__ __forceinline__ void mma16816(float* d, const uint32_t* a, const uint32_t* b) {
    asm volatile("mma.sync.aligned.m16n8k16.row.col.f32.f16.f16.f32 "
        "{%0,%1,%2,%3}, {%4,%5,%6,%7}, {%8,%9}, {%0,%1,%2,%3};"
        : "+f"(d[0]), "+f"(d[1]), "+f"(d[2]), "+f"(d[3])
        : "r"(a[0]), "r"(a[1]), "r"(a[2]), "r"(a[3]), "r"(b[0]), "r"(b[1]));
}

// ------------------------- fused conversion ---------------------------------
#define S_X   2097152
#define S_WQ  (S_X  + 1048576)
#define S_WK  (S_WQ + 262144)
#define S_WV  (S_WK + 262144)
#define S_ALL (S_WV + 262144)

__device__ __forceinline__ uint2 f4_to_h4(float4 v) {
    __half2 h[2];
    h[0] = __floats2half2_rn(v.x, v.y);
    h[1] = __floats2half2_rn(v.z, v.w);
    return *(uint2*)h;
}

__global__ void __launch_bounds__(256)
conv_all(const float* __restrict__ x, const float* __restrict__ Wq,
         const float* __restrict__ Wk, const float* __restrict__ Wv,
         const float* __restrict__ Wo, __half* __restrict__ xf,
         __half* __restrict__ wqkv, __half* __restrict__ wo)
{
    int i = blockIdx.x * 256 + threadIdx.x;
    if (i >= S_ALL) return;
    const float4* src; uint2* dst; int j;
    if (i < S_X)       { src = (const float4*)x;  dst = (uint2*)xf;   j = i; }
    else if (i < S_WQ) { src = (const float4*)Wq; dst = (uint2*)wqkv; j = i - S_X; }
    else if (i < S_WK) { src = (const float4*)Wk; dst = (uint2*)wqkv + 1048576; j = i - S_WQ; }
    else if (i < S_WV) { src = (const float4*)Wv; dst = (uint2*)wqkv + 1310720; j = i - S_WK; }
    else               { src = (const float4*)Wo; dst = (uint2*)wo;   j = i - S_WV; }
    dst[j] = f4_to_h4(src[j]);
}

// ------------------------- HMMA fp16 GEMM -----------------------------------
// C[m,n] = sum_k A[m,k]*W[n,k] + bias[n].  128x128 CTA tile, BK=64,
// 8 warps (warp grid 2 in M x 4 in N, warp tile 64x32 -> 64 acc regs),
// 3-stage cp.async, XOR-swizzled 128B rows, 2 CTAs/SM (16 warps, 4/SMSP).
#define GBK    64
#define TILEB  (128 * 128)          // 16384 B
#define STAGEB (2 * TILEB)
#define NSTG   3
#define GSMEM  (NSTG * STAGEB)      // 98304 B

template <typename OutT>
__global__ void __launch_bounds__(256, 2)
gemm_f16(const __half* __restrict__ A, const __half* __restrict__ W,
         const float* __restrict__ bias0, const float* __restrict__ bias1,
         const float* __restrict__ bias2, int nb1, int nb2,
         OutT* __restrict__ C, int N, int K)
{
    extern __shared__ __align__(16) char smem[];
    const uint32_t sb = smem_to_u32(smem);
    const int tid = threadIdx.x;
    const int lane = tid & 31;
    const int warp = tid >> 5;
    const int bm = blockIdx.y * 128;
    const int bn = blockIdx.x * 128;
    const int wm0 = (warp & 1) * 64;       // 2 warps in M
    const int wn0 = (warp >> 1) * 32;      // 4 warps in N

    float acc[4][4][4];
#pragma unroll
    for (int i = 0; i < 4; i++)
#pragma unroll
        for (int j = 0; j < 4; j++)
#pragma unroll
            for (int r = 0; r < 4; r++) acc[i][j][r] = 0.f;

    const int lrow = tid >> 3;     // 0..31
    const int lq   = tid & 7;

    auto load_chunk = [&](int stage, int ck) {
        const uint32_t stb = sb + stage * STAGEB;
        const size_t kof = (size_t)ck * GBK + lq * 8;
#pragma unroll
        for (int l = 0; l < 4; l++) {
            int row = lrow + l * 32;
            uint32_t dst = stb + row * 128 + ((lq ^ (row & 7)) << 4);
            cp16(dst,         A + (size_t)(bm + row) * K + kof);
            cp16(dst + TILEB, W + (size_t)(bn + row) * K + kof);
        }
    };

    const int arow[4] = {wm0 + 0 * 16 + (lane & 15), wm0 + 1 * 16 + (lane & 15),
                         wm0 + 2 * 16 + (lane & 15), wm0 + 3 * 16 + (lane & 15)};
    const int ahalf = lane >> 4;
    const int brow[2] = {wn0 + 0 * 16 + (lane & 7) + ((lane >> 4) << 3),
                         wn0 + 1 * 16 + (lane & 7) + ((lane >> 4) << 3)};
    const int bhalf = (lane >> 3) & 1;

    auto compute = [&](int stage) {
        const uint32_t tA = sb + stage * STAGEB;
        const uint32_t tW = tA + TILEB;
#pragma unroll
        for (int ks = 0; ks < 4; ks++) {
            uint32_t a[4][4], b[2][4];
#pragma unroll
            for (int rb = 0; rb < 4; rb++) {
                int r = arow[rb];
                uint32_t q = (uint32_t)((2 * ks + ahalf) ^ (r & 7));
                ldx4(a[rb], tA + (uint32_t)r * 128 + (q << 4));
            }
#pragma unroll
            for (int hb = 0; hb < 2; hb++) {
                int r = brow[hb];
                uint32_t q = (uint32_t)((2 * ks + bhalf) ^ (r & 7));
                ldx4(b[hb], tW + (uint32_t)r * 128 + (q << 4));
            }
#pragma unroll
            for (int rb = 0; rb < 4; rb++) {
#pragma unroll
                for (int nb = 0; nb < 4; nb++) {
                    mma16816(acc[rb][nb], a[rb], &b[nb >> 1][(nb & 1) * 2]);
                }
            }
        }
    };

    const int nchunk = K / GBK;   // 16
    load_chunk(0, 0); cp_commit();
    load_chunk(1, 1); cp_commit();
    for (int c = 0; c < nchunk; c++) {
        if (c == nchunk - 1) cp_wait0(); else cp_wait1();
        __syncthreads();
        if (c + 2 < nchunk) { load_chunk((c + 2) % NSTG, c + 2); cp_commit(); }
        compute(c % NSTG);
    }

    const float* bp; int segbase;
    if (bn < nb1)      { bp = bias0; segbase = 0;   }
    else if (bn < nb2) { bp = bias1; segbase = nb1; }
    else               { bp = bias2; segbase = nb2; }

#pragma unroll
    for (int rb = 0; rb < 4; rb++) {
#pragma unroll
        for (int nb = 0; nb < 4; nb++) {
            int row = bm + wm0 + rb * 16 + (lane >> 2);
            int col = bn + wn0 + nb * 8 + (lane & 3) * 2;
            float b0 = bp[col - segbase], b1 = bp[col - segbase + 1];
            float o0 = acc[rb][nb][0] + b0, o1 = acc[rb][nb][1] + b1;
            float o2 = acc[rb][nb][2] + b0, o3 = acc[rb][nb][3] + b1;
            if constexpr (sizeof(OutT) == 2) {
                __half2 h0 = __floats2half2_rn(o0, o1);
                __half2 h1 = __floats2half2_rn(o2, o3);
                *(__half2*)((__half*)C + (size_t)row * N + col)       = h0;
                *(__half2*)((__half*)C + (size_t)(row + 8) * N + col) = h1;
            } else {
                float2 v0 = {o0, o1}, v1 = {o2, o3};
                *(float2*)((float*)C + (size_t)row * N + col)       = v0;
                *(float2*)((float*)C + (size_t)(row + 8) * N + col) = v1;
            }
        }
    }
}

// ------------------------- per-token head-mixing attention ------------------
#define KSTR 68
__global__ void __launch_bounds__(256)
attn_kernel(const __half* __restrict__ gqkv, __half* __restrict__ gy)
{
    const int tok = blockIdx.x;
    const int t = threadIdx.x;
    const __half* base = gqkv + (size_t)tok * NQKV;

    __shared__ __align__(16) float qs[QN * HN * DH];
    __shared__ __align__(16) float ks[HN * KSTR];
    __shared__ __align__(16) float vs[HN * DH];
    __shared__ float sc[QN][HN][HN];
    __shared__ float ps[HN][HN];

    {
        const uint4* qg = (const uint4*)base;
#pragma unroll
        for (int l = 0; l < 2; l++) {
            uint4 p = qg[t + l * 256];
            const __half2* hp = (const __half2*)&p;
            float* dst = qs + (t + l * 256) * 8;
#pragma unroll
            for (int j = 0; j < 4; j++) {
                float2 f = __half22float2(hp[j]);
                dst[2 * j] = f.x; dst[2 * j + 1] = f.y;
            }
        }
    }
    if (t < 128) {
        uint4 p = ((const uint4*)(base + QCOLS))[t];
        const __half2* hp = (const __half2*)&p;
        int g = t >> 3, d = (t * 8) & 63;
        float* kr = ks + g * KSTR + d;
#pragma unroll
        for (int j = 0; j < 4; j++) {
            float2 f = __half22float2(hp[j]);
            kr[2 * j] = f.x; kr[2 * j + 1] = f.y;
        }
    } else {
        int tt = t - 128;
        uint4 p = ((const uint4*)(base + QCOLS + EDIM))[tt];
        const __half2* hp = (const __half2*)&p;
        int g = tt >> 3, d = (tt * 8) & 63;
        float* vr = vs + g * DH + d;
#pragma unroll
        for (int j = 0; j < 4; j++) {
            float2 f = __half22float2(hp[j]);
            vr[2 * j] = f.x; vr[2 * j + 1] = f.y;
        }
    }
    __syncthreads();

    const float scale = 0.125f;
#pragma unroll
    for (int l = 0; l < 4; l++) {
        int e = t + l * 256;
        int qq = e >> 8, h = (e >> 4) & 15, g = e & 15;
        const float4* qp4 = (const float4*)(qs + (qq * HN + h) * DH);
        const float4* kp4 = (const float4*)(ks + g * KSTR);
        float s_ = 0.f;
#pragma unroll
        for (int d = 0; d < 16; d++) {
            float4 a = qp4[d], b = kp4[d];
            s_ += a.x * b.x + a.y * b.y + a.z * b.z + a.w * b.w;
        }
        sc[qq][h][g] = s_ * scale;
    }
    __syncthreads();

    if (t < 64) {
        int qq = t >> 4, h = t & 15;
        float* row = sc[qq][h];
        float m = row[0];
#pragma unroll
        for (int g = 1; g < 16; g++) m = fmaxf(m, row[g]);
        float ssum = 0.f;
#pragma unroll
        for (int g = 0; g < 16; g++) { float ex = __expf(row[g] - m); row[g] = ex; ssum += ex; }
        float inv = 1.f / ssum;
#pragma unroll
        for (int g = 0; g < 16; g++) row[g] *= inv;
    }
    __syncthreads();

    {
        int h = t >> 4, g = t & 15;
        ps[h][g] = sc[0][h][g] + sc[1][h][g] + sc[2][h][g] + sc[3][h][g];
    }
    __syncthreads();

    const int b = tok >> 11, s = tok & 2047;
    {
        int h = t >> 4;
        int d0 = (t * 4) & 63;
        const float4* vp4 = (const float4*)vs;
        float4 o = {0.f, 0.f, 0.f, 0.f};
#pragma unroll
        for (int g = 0; g < 16; g++) {
            float p = ps[h][g];
            float4 vv = vp4[g * 16 + (d0 >> 2)];
            o.x = fmaf(p, vv.x, o.x); o.y = fmaf(p, vv.y, o.y);
            o.z = fmaf(p, vv.z, o.z); o.w = fmaf(p, vv.w, o.w);
        }
        __half2 h0 = __floats2half2_rn(o.x, o.y);
        __half2 h1 = __floats2half2_rn(o.z, o.w);
        size_t oi = (((size_t)b * HN + h) * SEQ + s) * DH + d0;
        *(__half2*)(gy + oi)     = h0;
        *(__half2*)(gy + oi + 2) = h1;
    }
}

// ------------------------- launch -------------------------------------------
extern "C" void kernel_launch(void* const* d_in, const int* in_sizes, int n_in,
                              void* d_out, int out_size)
{
    const float* x  = (const float*)d_in[0];
    const float* Wq = (const float*)d_in[1];
    const float* bq = (const float*)d_in[2];
    const float* Wk = (const float*)d_in[3];
    const float* bk = (const float*)d_in[4];
    const float* Wv = (const float*)d_in[5];
    const float* bv = (const float*)d_in[6];
    const float* Wo = (const float*)d_in[7];
    const float* bo = (const float*)d_in[8];
    float* out = (float*)d_out;
    (void)in_sizes; (void)n_in; (void)out_size;

    __half *qkv, *xf, *gy, *wqkv, *wo;
    cudaGetSymbolAddress((void**)&qkv, g_qkv);
    cudaGetSymbolAddress((void**)&xf, g_xf);
    cudaGetSymbolAddress((void**)&gy, g_y);
    cudaGetSymbolAddress((void**)&wqkv, g_wqkv);
    cudaGetSymbolAddress((void**)&wo, g_wo);

    cudaFuncSetAttribute(gemm_f16<float>,  cudaFuncAttributeMaxDynamicSharedMemorySize, GSMEM);
    cudaFuncSetAttribute(gemm_f16<__half>, cudaFuncAttributeMaxDynamicSharedMemorySize, GSMEM);

    // 1) fused fp32 -> fp16 conversions
    conv_all<<<(S_ALL + 255) / 256, 256>>>(x, Wq, Wk, Wv, Wo, xf, wqkv, wo);

    // 2) fused QKV projection (N = 6144)
    gemm_f16<__half><<<dim3(NQKV / 128, NTOK / 128), 256, GSMEM>>>(
        xf, wqkv, bq, bk, bv, QCOLS, QCOLS + EDIM, qkv, NQKV, EDIM);

    // 3) per-token attention -> y fp16 ((B,H,S,D) flat == (B,S,E) flat)
    attn_kernel<<<NTOK, 256>>>(qkv, gy);

    // 4) output projection (fp32 out)
    gemm_f16<float><<<dim3(EDIM / 128, NTOK / 128), 256, GSMEM>>>(
        gy, wo, bo, bo, bo, 1 << 30, 1 << 30, out, EDIM, EDIM);
}

// round 15
// speedup vs baseline: 1.0691x; 1.0306x over previous
#include <cuda_runtime.h>
#include <cuda_fp16.h>
#include <cstdint>

#define BATCH 4
#define SEQ   2048
#define EDIM  1024
#define QN    4
#define HN    16
#define DH    64
#define NTOK  (BATCH*SEQ)        // 8192
#define QCOLS (QN*EDIM)          // 4096
#define NQKV  (QCOLS + 2*EDIM)   // 6144

// ------------------------- scratch (static, no runtime alloc) ---------------
__device__ __half g_qkv[(size_t)NTOK * NQKV];
__device__ __half g_xf[(size_t)NTOK * EDIM];
__device__ __half g_y[(size_t)NTOK * EDIM];
__device__ __half g_wqkv[(size_t)NQKV * EDIM];
__device__ __half g_wo[(size_t)EDIM * EDIM];

// ------------------------- helpers ------------------------------------------
__device__ __forceinline__ uint32_t smem_to_u32(const void* p) {
    uint32_t a;
    asm("{ .reg .u64 t; cvta.to.shared.u64 t, %1; cvt.u32.u64 %0, t; }" : "=r"(a) : "l"(p));
    return a;
}
__device__ __forceinline__ void cp16(uint32_t dst, const void* src) {
    asm volatile("cp.async.cg.shared.global [%0], [%1], 16;" :: "r"(dst), "l"(src));
}
__device__ __forceinline__ void cp_commit() { asm volatile("cp.async.commit_group;" ::: "memory"); }
__device__ __forceinline__ void cp_wait0()  { asm volatile("cp.async.wait_group 0;"  ::: "memory"); }
__device__ __forceinline__ void cp_wait1()  { asm volatile("cp.async.wait_group 1;"  ::: "memory"); }
__device__ __forceinline__ void ldx4(uint32_t* r, uint32_t addr) {
    asm volatile("ldmatrix.sync.aligned.m8n8.x4.shared.b16 {%0,%1,%2,%3}, [%4];"
        : "=r"(r[0]), "=r"(r[1]), "=r"(r[2]), "=r"(r[3]) : "r"(addr));
}
__device__ __forceinline__ void mma16816(float* d, const uint32_t* a, const uint32_t* b) {
    asm volatile("mma.sync.aligned.m16n8k16.row.col.f32.f16.f16.f32 "
        "{%0,%1,%2,%3}, {%4,%5,%6,%7}, {%8,%9}, {%0,%1,%2,%3};"
        : "+f"(d[0]), "+f"(d[1]), "+f"(d[2]), "+f"(d[3])
        : "r"(a[0]), "r"(a[1]), "r"(a[2]), "r"(a[3]), "r"(b[0]), "r"(b[1]));
}

// ------------------------- fused conversion (MLP=4 grid-stride) -------------
#define S_X   2097152
#define S_WQ  (S_X  + 1048576)
#define S_WK  (S_WQ + 262144)
#define S_WV  (S_WK + 262144)
#define S_ALL (S_WV + 262144)

__device__ __forceinline__ uint2 f4_to_h4(float4 v) {
    __half2 h[2];
    h[0] = __floats2half2_rn(v.x, v.y);
    h[1] = __floats2half2_rn(v.z, v.w);
    return *(uint2*)h;
}

__device__ __forceinline__ void conv_route(int i, const float* x, const float* Wq,
                                           const float* Wk, const float* Wv,
                                           const float* Wo, __half* xf,
                                           __half* wqkv, __half* wo,
                                           const float4*& src, uint2*& dst, int& j)
{
    if (i < S_X)       { src = (const float4*)x;  dst = (uint2*)xf;   j = i; }
    else if (i < S_WQ) { src = (const float4*)Wq; dst = (uint2*)wqkv; j = i - S_X; }
    else if (i < S_WK) { src = (const float4*)Wk; dst = (uint2*)wqkv + 1048576; j = i - S_WQ; }
    else if (i < S_WV) { src = (const float4*)Wv; dst = (uint2*)wqkv + 1310720; j = i - S_WK; }
    else               { src = (const float4*)Wo; dst = (uint2*)wo;   j = i - S_WV; }
}

__global__ void __launch_bounds__(256)
conv_all(const float* __restrict__ x, const float* __restrict__ Wq,
         const float* __restrict__ Wk, const float* __restrict__ Wv,
         const float* __restrict__ Wo, __half* __restrict__ xf,
         __half* __restrict__ wqkv, __half* __restrict__ wo)
{
    const int stride = gridDim.x * 256;
    int i0 = blockIdx.x * 256 + threadIdx.x;
    // 4 independent load slots in flight per thread (MLP=4)
    const float4* s[4]; uint2* d[4]; int j[4]; float4 v[4]; int n = 0;
#pragma unroll
    for (int l = 0; l < 4; l++) {
        int i = i0 + l * stride;
        if (i < S_ALL) {
            conv_route(i, x, Wq, Wk, Wv, Wo, xf, wqkv, wo, s[n], d[n], j[n]);
            v[n] = s[n][j[n]];
            n++;
        }
    }
#pragma unroll
    for (int l = 0; l < 4; l++)
        if (l < n) d[l][j[l]] = f4_to_h4(v[l]);
}

// ------------------------- HMMA fp16 GEMM (R8 config) -----------------------
// C[m,n] = sum_k A[m,k]*W[n,k] + bias[n].  128x128 CTA tile, BK=64,
// 4 warps (warp tile 64x64), 3-stage cp.async (2 chunks in flight),
// XOR-swizzled 128B rows: quarter q of row r stored at q ^ (r & 7).
#define GBK    64
#define TILEB  (128 * 128)
#define STAGEB (2 * TILEB)
#define NSTG   3
#define GSMEM  (NSTG * STAGEB)      // 98304 B

template <typename OutT>
__global__ void __launch_bounds__(128, 2)
gemm_f16(const __half* __restrict__ A, const __half* __restrict__ W,
         const float* __restrict__ bias0, const float* __restrict__ bias1,
         const float* __restrict__ bias2, int nb1, int nb2,
         OutT* __restrict__ C, int N, int K)
{
    extern __shared__ __align__(16) char smem[];
    const uint32_t sb = smem_to_u32(smem);
    const int tid = threadIdx.x;
    const int lane = tid & 31;
    const int warp = tid >> 5;
    const int bm = blockIdx.y * 128;
    const int bn = blockIdx.x * 128;
    const int wm0 = (warp & 1) * 64;
    const int wn0 = (warp >> 1) * 64;

    float acc[4][8][4];
#pragma unroll
    for (int i = 0; i < 4; i++)
#pragma unroll
        for (int j = 0; j < 8; j++)
#pragma unroll
            for (int r = 0; r < 4; r++) acc[i][j][r] = 0.f;

    const int lrow = tid >> 3;     // 0..15
    const int lq   = tid & 7;

    auto load_chunk = [&](int stage, int ck) {
        const uint32_t stb = sb + stage * STAGEB;
        const size_t kof = (size_t)ck * GBK + lq * 8;
#pragma unroll
        for (int l = 0; l < 8; l++) {
            int row = lrow + l * 16;
            uint32_t dst = stb + row * 128 + ((lq ^ (row & 7)) << 4);
            cp16(dst,         A + (size_t)(bm + row) * K + kof);
            cp16(dst + TILEB, W + (size_t)(bn + row) * K + kof);
        }
    };

    const int arow[4] = {wm0 + 0 * 16 + (lane & 15), wm0 + 1 * 16 + (lane & 15),
                         wm0 + 2 * 16 + (lane & 15), wm0 + 3 * 16 + (lane & 15)};
    const int ahalf = lane >> 4;
    const int brow[4] = {wn0 + 0 * 16 + (lane & 7) + ((lane >> 4) << 3),
                         wn0 + 1 * 16 + (lane & 7) + ((lane >> 4) << 3),
                         wn0 + 2 * 16 + (lane & 7) + ((lane >> 4) << 3),
                         wn0 + 3 * 16 + (lane & 7) + ((lane >> 4) << 3)};
    const int bhalf = (lane >> 3) & 1;

    auto compute = [&](int stage) {
        const uint32_t tA = sb + stage * STAGEB;
        const uint32_t tW = tA + TILEB;
#pragma unroll
        for (int ks = 0; ks < 4; ks++) {
            uint32_t a[4][4], b[4][4];
#pragma unroll
            for (int rb = 0; rb < 4; rb++) {
                int r = arow[rb];
                uint32_t q = (uint32_t)((2 * ks + ahalf) ^ (r & 7));
                ldx4(a[rb], tA + (uint32_t)r * 128 + (q << 4));
            }
#pragma unroll
            for (int hb = 0; hb < 4; hb++) {
                int r = brow[hb];
                uint32_t q = (uint32_t)((2 * ks + bhalf) ^ (r & 7));
                ldx4(b[hb], tW + (uint32_t)r * 128 + (q << 4));
            }
#pragma unroll
            for (int rb = 0; rb < 4; rb++) {
#pragma unroll
                for (int nb = 0; nb < 8; nb++) {
                    mma16816(acc[rb][nb], a[rb], &b[nb >> 1][(nb & 1) * 2]);
                }
            }
        }
    };

    const int nchunk = K / GBK;   // 16
    load_chunk(0, 0); cp_commit();
    load_chunk(1, 1); cp_commit();
    for (int c = 0; c < nchunk; c++) {
        if (c == nchunk - 1) cp_wait0(); else cp_wait1();
        __syncthreads();
        if (c + 2 < nchunk) { load_chunk((c + 2) % NSTG, c + 2); cp_commit(); }
        compute(c % NSTG);
    }

    const float* bp; int segbase;
    if (bn < nb1)      { bp = bias0; segbase = 0;   }
    else if (bn < nb2) { bp = bias1; segbase = nb1; }
    else               { bp = bias2; segbase = nb2; }

#pragma unroll
    for (int rb = 0; rb < 4; rb++) {
#pragma unroll
        for (int nb = 0; nb < 8; nb++) {
            int row = bm + wm0 + rb * 16 + (lane >> 2);
            int col = bn + wn0 + nb * 8 + (lane & 3) * 2;
            float b0 = bp[col - segbase], b1 = bp[col - segbase + 1];
            float o0 = acc[rb][nb][0] + b0, o1 = acc[rb][nb][1] + b1;
            float o2 = acc[rb][nb][2] + b0, o3 = acc[rb][nb][3] + b1;
            if constexpr (sizeof(OutT) == 2) {
                __half2 h0 = __floats2half2_rn(o0, o1);
                __half2 h1 = __floats2half2_rn(o2, o3);
                *(__half2*)((__half*)C + (size_t)row * N + col)       = h0;
                *(__half2*)((__half*)C + (size_t)(row + 8) * N + col) = h1;
            } else {
                float2 v0 = {o0, o1}, v1 = {o2, o3};
                *(float2*)((float*)C + (size_t)row * N + col)       = v0;
                *(float2*)((float*)C + (size_t)(row + 8) * N + col) = v1;
            }
        }
    }
}

// ------------------------- per-token head-mixing attention ------------------
#define KSTR 68
__global__ void __launch_bounds__(256)
attn_kernel(const __half* __restrict__ gqkv, __half* __restrict__ gy)
{
    const int tok = blockIdx.x;
    const int t = threadIdx.x;
    const __half* base = gqkv + (size_t)tok * NQKV;

    __shared__ __align__(16) float qs[QN * HN * DH];
    __shared__ __align__(16) float ks[HN * KSTR];
    __shared__ __align__(16) float vs[HN * DH];
    __shared__ float sc[QN][HN][HN];
    __shared__ float ps[HN][HN];

    {
        const uint4* qg = (const uint4*)base;
#pragma unroll
        for (int l = 0; l < 2; l++) {
            uint4 p = qg[t + l * 256];
            const __half2* hp = (const __half2*)&p;
            float* dst = qs + (t + l * 256) * 8;
#pragma unroll
            for (int j = 0; j < 4; j++) {
                float2 f = __half22float2(hp[j]);
                dst[2 * j] = f.x; dst[2 * j + 1] = f.y;
            }
        }
    }
    if (t < 128) {
        uint4 p = ((const uint4*)(base + QCOLS))[t];
        const __half2* hp = (const __half2*)&p;
        int g = t >> 3, d = (t * 8) & 63;
        float* kr = ks + g * KSTR + d;
#pragma unroll
        for (int j = 0; j < 4; j++) {
            float2 f = __half22float2(hp[j]);
            kr[2 * j] = f.x; kr[2 * j + 1] = f.y;
        }
    } else {
        int tt = t - 128;
        uint4 p = ((const uint4*)(base + QCOLS + EDIM))[tt];
        const __half2* hp = (const __half2*)&p;
        int g = tt >> 3, d = (tt * 8) & 63;
        float* vr = vs + g * DH + d;
#pragma unroll
        for (int j = 0; j < 4; j++) {
            float2 f = __half22float2(hp[j]);
            vr[2 * j] = f.x; vr[2 * j + 1] = f.y;
        }
    }
    __syncthreads();

    const float scale = 0.125f;
#pragma unroll
    for (int l = 0; l < 4; l++) {
        int e = t + l * 256;
        int qq = e >> 8, h = (e >> 4) & 15, g = e & 15;
        const float4* qp4 = (const float4*)(qs + (qq * HN + h) * DH);
        const float4* kp4 = (const float4*)(ks + g * KSTR);
        float s_ = 0.f;
#pragma unroll
        for (int d = 0; d < 16; d++) {
            float4 a = qp4[d], b = kp4[d];
            s_ += a.x * b.x + a.y * b.y + a.z * b.z + a.w * b.w;
        }
        sc[qq][h][g] = s_ * scale;
    }
    __syncthreads();

    if (t < 64) {
        int qq = t >> 4, h = t & 15;
        float* row = sc[qq][h];
        float m = row[0];
#pragma unroll
        for (int g = 1; g < 16; g++) m = fmaxf(m, row[g]);
        float ssum = 0.f;
#pragma unroll
        for (int g = 0; g < 16; g++) { float ex = __expf(row[g] - m); row[g] = ex; ssum += ex; }
        float inv = 1.f / ssum;
#pragma unroll
        for (int g = 0; g < 16; g++) row[g] *= inv;
    }
    __syncthreads();

    {
        int h = t >> 4, g = t & 15;
        ps[h][g] = sc[0][h][g] + sc[1][h][g] + sc[2][h][g] + sc[3][h][g];
    }
    __syncthreads();

    const int b = tok >> 11, s = tok & 2047;
    {
        int h = t >> 4;
        int d0 = (t * 4) & 63;
        const float4* vp4 = (const float4*)vs;
        float4 o = {0.f, 0.f, 0.f, 0.f};
#pragma unroll
        for (int g = 0; g < 16; g++) {
            float p = ps[h][g];
            float4 vv = vp4[g * 16 + (d0 >> 2)];
            o.x = fmaf(p, vv.x, o.x); o.y = fmaf(p, vv.y, o.y);
            o.z = fmaf(p, vv.z, o.z); o.w = fmaf(p, vv.w, o.w);
        }
        __half2 h0 = __floats2half2_rn(o.x, o.y);
        __half2 h1 = __floats2half2_rn(o.z, o.w);
        size_t oi = (((size_t)b * HN + h) * SEQ + s) * DH + d0;
        *(__half2*)(gy + oi)     = h0;
        *(__half2*)(gy + oi + 2) = h1;
    }
}

// ------------------------- launch -------------------------------------------
extern "C" void kernel_launch(void* const* d_in, const int* in_sizes, int n_in,
                              void* d_out, int out_size)
{
    const float* x  = (const float*)d_in[0];
    const float* Wq = (const float*)d_in[1];
    const float* bq = (const float*)d_in[2];
    const float* Wk = (const float*)d_in[3];
    const float* bk = (const float*)d_in[4];
    const float* Wv = (const float*)d_in[5];
    const float* bv = (const float*)d_in[6];
    const float* Wo = (const float*)d_in[7];
    const float* bo = (const float*)d_in[8];
    float* out = (float*)d_out;
    (void)in_sizes; (void)n_in; (void)out_size;

    __half *qkv, *xf, *gy, *wqkv, *wo;
    cudaGetSymbolAddress((void**)&qkv, g_qkv);
    cudaGetSymbolAddress((void**)&xf, g_xf);
    cudaGetSymbolAddress((void**)&gy, g_y);
    cudaGetSymbolAddress((void**)&wqkv, g_wqkv);
    cudaGetSymbolAddress((void**)&wo, g_wo);

    cudaFuncSetAttribute(gemm_f16<float>,  cudaFuncAttributeMaxDynamicSharedMemorySize, GSMEM);
    cudaFuncSetAttribute(gemm_f16<__half>, cudaFuncAttributeMaxDynamicSharedMemorySize, GSMEM);

    // 1) fused fp32 -> fp16 conversions, MLP=4 grid-stride
    {
        int threads_needed = (S_ALL + 3) / 4;
        int blocks = (threads_needed + 255) / 256;
        conv_all<<<blocks, 256>>>(x, Wq, Wk, Wv, Wo, xf, wqkv, wo);
    }

    // 2) fused QKV projection (N = 6144), bias segment-selected per CTA
    gemm_f16<__half><<<dim3(NQKV / 128, NTOK / 128), 128, GSMEM>>>(
        xf, wqkv, bq, bk, bv, QCOLS, QCOLS + EDIM, qkv, NQKV, EDIM);

    // 3) per-token attention -> y fp16 ((B,H,S,D) flat == (B,S,E) flat)
    attn_kernel<<<NTOK, 256>>>(qkv, gy);

    // 4) output projection (fp32 out)
    gemm_f16<float><<<dim3(EDIM / 128, NTOK / 128), 128, GSMEM>>>(
        gy, wo, bo, bo, bo, 1 << 30, 1 << 30, out, EDIM, EDIM);
}

// round 16
// speedup vs baseline: 1.1230x; 1.0504x over previous
#include <cuda_runtime.h>
#include <cuda_fp16.h>
#include <cstdint>

#define BATCH 4
#define SEQ   2048
#define EDIM  1024
#define QN    4
#define HN    16
#define DH    64
#define NTOK  (BATCH*SEQ)        // 8192
#define QCOLS (QN*EDIM)          // 4096
#define NQKV  (QCOLS + 2*EDIM)   // 6144

// ------------------------- scratch (static, no runtime alloc) ---------------
__device__ __half g_qkv[(size_t)NTOK * NQKV];
__device__ __half g_xf[(size_t)NTOK * EDIM];
__device__ __half g_y[(size_t)NTOK * EDIM];
__device__ __half g_wqkv[(size_t)NQKV * EDIM];
__device__ __half g_wo[(size_t)EDIM * EDIM];

// ------------------------- helpers ------------------------------------------
__device__ __forceinline__ uint32_t smem_to_u32(const void* p) {
    uint32_t a;
    asm("{ .reg .u64 t; cvta.to.shared.u64 t, %1; cvt.u32.u64 %0, t; }" : "=r"(a) : "l"(p));
    return a;
}
__device__ __forceinline__ void cp16(uint32_t dst, const void* src) {
    asm volatile("cp.async.cg.shared.global [%0], [%1], 16;" :: "r"(dst), "l"(src));
}
__device__ __forceinline__ void cp_commit() { asm volatile("cp.async.commit_group;" ::: "memory"); }
__device__ __forceinline__ void cp_wait0()  { asm volatile("cp.async.wait_group 0;"  ::: "memory"); }
__device__ __forceinline__ void cp_wait1()  { asm volatile("cp.async.wait_group 1;"  ::: "memory"); }
__device__ __forceinline__ void ldx4(uint32_t* r, uint32_t addr) {
    asm volatile("ldmatrix.sync.aligned.m8n8.x4.shared.b16 {%0,%1,%2,%3}, [%4];"
        : "=r"(r[0]), "=r"(r[1]), "=r"(r[2]), "=r"(r[3]) : "r"(addr));
}
__device__ __forceinline__ void mma16816(float* d, const uint32_t* a, const uint32_t* b) {
    asm volatile("mma.sync.aligned.m16n8k16.row.col.f32.f16.f16.f32 "
        "{%0,%1,%2,%3}, {%4,%5,%6,%7}, {%8,%9}, {%0,%1,%2,%3};"
        : "+f"(d[0]), "+f"(d[1]), "+f"(d[2]), "+f"(d[3])
        : "r"(a[0]), "r"(a[1]), "r"(a[2]), "r"(a[3]), "r"(b[0]), "r"(b[1]));
}

// ------------------------- fused conversion (R8 original) -------------------
#define S_X   2097152
#define S_WQ  (S_X  + 1048576)
#define S_WK  (S_WQ + 262144)
#define S_WV  (S_WK + 262144)
#define S_ALL (S_WV + 262144)

__device__ __forceinline__ uint2 f4_to_h4(float4 v) {
    __half2 h[2];
    h[0] = __floats2half2_rn(v.x, v.y);
    h[1] = __floats2half2_rn(v.z, v.w);
    return *(uint2*)h;
}

__global__ void __launch_bounds__(256)
conv_all(const float* __restrict__ x, const float* __restrict__ Wq,
         const float* __restrict__ Wk, const float* __restrict__ Wv,
         const float* __restrict__ Wo, __half* __restrict__ xf,
         __half* __restrict__ wqkv, __half* __restrict__ wo)
{
    int i = blockIdx.x * 256 + threadIdx.x;
    if (i >= S_ALL) return;
    const float4* src; uint2* dst; int j;
    if (i < S_X)       { src = (const float4*)x;  dst = (uint2*)xf;   j = i; }
    else if (i < S_WQ) { src = (const float4*)Wq; dst = (uint2*)wqkv; j = i - S_X; }
    else if (i < S_WK) { src = (const float4*)Wk; dst = (uint2*)wqkv + 1048576; j = i - S_WQ; }
    else if (i < S_WV) { src = (const float4*)Wv; dst = (uint2*)wqkv + 1310720; j = i - S_WK; }
    else               { src = (const float4*)Wo; dst = (uint2*)wo;   j = i - S_WV; }
    dst[j] = f4_to_h4(src[j]);
}

// ------------------------- HMMA fp16 GEMM (R8 config, unchanged) ------------
#define GBK    64
#define TILEB  (128 * 128)
#define STAGEB (2 * TILEB)
#define NSTG   3
#define GSMEM  (NSTG * STAGEB)      // 98304 B

template <typename OutT>
__global__ void __launch_bounds__(128, 2)
gemm_f16(const __half* __restrict__ A, const __half* __restrict__ W,
         const float* __restrict__ bias0, const float* __restrict__ bias1,
         const float* __restrict__ bias2, int nb1, int nb2,
         OutT* __restrict__ C, int N, int K)
{
    extern __shared__ __align__(16) char smem[];
    const uint32_t sb = smem_to_u32(smem);
    const int tid = threadIdx.x;
    const int lane = tid & 31;
    const int warp = tid >> 5;
    const int bm = blockIdx.y * 128;
    const int bn = blockIdx.x * 128;
    const int wm0 = (warp & 1) * 64;
    const int wn0 = (warp >> 1) * 64;

    float acc[4][8][4];
#pragma unroll
    for (int i = 0; i < 4; i++)
#pragma unroll
        for (int j = 0; j < 8; j++)
#pragma unroll
            for (int r = 0; r < 4; r++) acc[i][j][r] = 0.f;

    const int lrow = tid >> 3;     // 0..15
    const int lq   = tid & 7;

    auto load_chunk = [&](int stage, int ck) {
        const uint32_t stb = sb + stage * STAGEB;
        const size_t kof = (size_t)ck * GBK + lq * 8;
#pragma unroll
        for (int l = 0; l < 8; l++) {
            int row = lrow + l * 16;
            uint32_t dst = stb + row * 128 + ((lq ^ (row & 7)) << 4);
            cp16(dst,         A + (size_t)(bm + row) * K + kof);
            cp16(dst + TILEB, W + (size_t)(bn + row) * K + kof);
        }
    };

    const int arow[4] = {wm0 + 0 * 16 + (lane & 15), wm0 + 1 * 16 + (lane & 15),
                         wm0 + 2 * 16 + (lane & 15), wm0 + 3 * 16 + (lane & 15)};
    const int ahalf = lane >> 4;
    const int brow[4] = {wn0 + 0 * 16 + (lane & 7) + ((lane >> 4) << 3),
                         wn0 + 1 * 16 + (lane & 7) + ((lane >> 4) << 3),
                         wn0 + 2 * 16 + (lane & 7) + ((lane >> 4) << 3),
                         wn0 + 3 * 16 + (lane & 7) + ((lane >> 4) << 3)};
    const int bhalf = (lane >> 3) & 1;

    auto compute = [&](int stage) {
        const uint32_t tA = sb + stage * STAGEB;
        const uint32_t tW = tA + TILEB;
#pragma unroll
        for (int ks = 0; ks < 4; ks++) {
            uint32_t a[4][4], b[4][4];
#pragma unroll
            for (int rb = 0; rb < 4; rb++) {
                int r = arow[rb];
                uint32_t q = (uint32_t)((2 * ks + ahalf) ^ (r & 7));
                ldx4(a[rb], tA + (uint32_t)r * 128 + (q << 4));
            }
#pragma unroll
            for (int hb = 0; hb < 4; hb++) {
                int r = brow[hb];
                uint32_t q = (uint32_t)((2 * ks + bhalf) ^ (r & 7));
                ldx4(b[hb], tW + (uint32_t)r * 128 + (q << 4));
            }
#pragma unroll
            for (int rb = 0; rb < 4; rb++) {
#pragma unroll
                for (int nb = 0; nb < 8; nb++) {
                    mma16816(acc[rb][nb], a[rb], &b[nb >> 1][(nb & 1) * 2]);
                }
            }
        }
    };

    const int nchunk = K / GBK;   // 16
    load_chunk(0, 0); cp_commit();
    load_chunk(1, 1); cp_commit();
    for (int c = 0; c < nchunk; c++) {
        if (c == nchunk - 1) cp_wait0(); else cp_wait1();
        __syncthreads();
        if (c + 2 < nchunk) { load_chunk((c + 2) % NSTG, c + 2); cp_commit(); }
        compute(c % NSTG);
    }

    const float* bp; int segbase;
    if (bn < nb1)      { bp = bias0; segbase = 0;   }
    else if (bn < nb2) { bp = bias1; segbase = nb1; }
    else               { bp = bias2; segbase = nb2; }

#pragma unroll
    for (int rb = 0; rb < 4; rb++) {
#pragma unroll
        for (int nb = 0; nb < 8; nb++) {
            int row = bm + wm0 + rb * 16 + (lane >> 2);
            int col = bn + wn0 + nb * 8 + (lane & 3) * 2;
            float b0 = bp[col - segbase], b1 = bp[col - segbase + 1];
            float o0 = acc[rb][nb][0] + b0, o1 = acc[rb][nb][1] + b1;
            float o2 = acc[rb][nb][2] + b0, o3 = acc[rb][nb][3] + b1;
            if constexpr (sizeof(OutT) == 2) {
                __half2 h0 = __floats2half2_rn(o0, o1);
                __half2 h1 = __floats2half2_rn(o2, o3);
                *(__half2*)((__half*)C + (size_t)row * N + col)       = h0;
                *(__half2*)((__half*)C + (size_t)(row + 8) * N + col) = h1;
            } else {
                float2 v0 = {o0, o1}, v1 = {o2, o3};
                *(float2*)((float*)C + (size_t)row * N + col)       = v0;
                *(float2*)((float*)C + (size_t)(row + 8) * N + col) = v1;
            }
        }
    }
}

// ------------------------- per-token head-mixing attention ------------------
// Score phase restructured: thread t owns (h,g) fixed and all 4 qq values,
// so each k float4 is loaded ONCE and reused across the 4 q rows
// (80 LDS.128/thread vs 128 before). Per-score FMA chain order unchanged.
#define KSTR 68
__global__ void __launch_bounds__(256)
attn_kernel(const __half* __restrict__ gqkv, __half* __restrict__ gy)
{
    const int tok = blockIdx.x;
    const int t = threadIdx.x;
    const __half* base = gqkv + (size_t)tok * NQKV;

    __shared__ __align__(16) float qs[QN * HN * DH];
    __shared__ __align__(16) float ks[HN * KSTR];
    __shared__ __align__(16) float vs[HN * DH];
    __shared__ float sc[QN][HN][HN];
    __shared__ float ps[HN][HN];

    {
        const uint4* qg = (const uint4*)base;
#pragma unroll
        for (int l = 0; l < 2; l++) {
            uint4 p = qg[t + l * 256];
            const __half2* hp = (const __half2*)&p;
            float* dst = qs + (t + l * 256) * 8;
#pragma unroll
            for (int j = 0; j < 4; j++) {
                float2 f = __half22float2(hp[j]);
                dst[2 * j] = f.x; dst[2 * j + 1] = f.y;
            }
        }
    }
    if (t < 128) {
        uint4 p = ((const uint4*)(base + QCOLS))[t];
        const __half2* hp = (const __half2*)&p;
        int g = t >> 3, d = (t * 8) & 63;
        float* kr = ks + g * KSTR + d;
#pragma unroll
        for (int j = 0; j < 4; j++) {
            float2 f = __half22float2(hp[j]);
            kr[2 * j] = f.x; kr[2 * j + 1] = f.y;
        }
    } else {
        int tt = t - 128;
        uint4 p = ((const uint4*)(base + QCOLS + EDIM))[tt];
        const __half2* hp = (const __half2*)&p;
        int g = tt >> 3, d = (tt * 8) & 63;
        float* vr = vs + g * DH + d;
#pragma unroll
        for (int j = 0; j < 4; j++) {
            float2 f = __half22float2(hp[j]);
            vr[2 * j] = f.x; vr[2 * j + 1] = f.y;
        }
    }
    __syncthreads();

    // scores: thread t -> (h, g) = ((t>>4)&15, t&15), all 4 qq
    const float scale = 0.125f;
    {
        const int h = (t >> 4) & 15, g = t & 15;
        const float4* kp4 = (const float4*)(ks + g * KSTR);
        const float4* qp4[QN];
#pragma unroll
        for (int qq = 0; qq < QN; qq++)
            qp4[qq] = (const float4*)(qs + (qq * HN + h) * DH);
        float s_[QN] = {0.f, 0.f, 0.f, 0.f};
#pragma unroll
        for (int d = 0; d < 16; d++) {
            float4 b = kp4[d];
#pragma unroll
            for (int qq = 0; qq < QN; qq++) {
                float4 a = qp4[qq][d];
                s_[qq] += a.x * b.x + a.y * b.y + a.z * b.z + a.w * b.w;
            }
        }
#pragma unroll
        for (int qq = 0; qq < QN; qq++)
            sc[qq][h][g] = s_[qq] * scale;
    }
    __syncthreads();

    if (t < 64) {
        int qq = t >> 4, h = t & 15;
        float* row = sc[qq][h];
        float m = row[0];
#pragma unroll
        for (int g = 1; g < 16; g++) m = fmaxf(m, row[g]);
        float ssum = 0.f;
#pragma unroll
        for (int g = 0; g < 16; g++) { float ex = __expf(row[g] - m); row[g] = ex; ssum += ex; }
        float inv = 1.f / ssum;
#pragma unroll
        for (int g = 0; g < 16; g++) row[g] *= inv;
    }
    __syncthreads();

    {
        int h = t >> 4, g = t & 15;
        ps[h][g] = sc[0][h][g] + sc[1][h][g] + sc[2][h][g] + sc[3][h][g];
    }
    __syncthreads();

    const int b = tok >> 11, s = tok & 2047;
    {
        int h = t >> 4;
        int d0 = (t * 4) & 63;
        const float4* vp4 = (const float4*)vs;
        float4 o = {0.f, 0.f, 0.f, 0.f};
#pragma unroll
        for (int g = 0; g < 16; g++) {
            float p = ps[h][g];
            float4 vv = vp4[g * 16 + (d0 >> 2)];
            o.x = fmaf(p, vv.x, o.x); o.y = fmaf(p, vv.y, o.y);
            o.z = fmaf(p, vv.z, o.z); o.w = fmaf(p, vv.w, o.w);
        }
        __half2 h0 = __floats2half2_rn(o.x, o.y);
        __half2 h1 = __floats2half2_rn(o.z, o.w);
        size_t oi = (((size_t)b * HN + h) * SEQ + s) * DH + d0;
        *(__half2*)(gy + oi)     = h0;
        *(__half2*)(gy + oi + 2) = h1;
    }
}

// ------------------------- launch -------------------------------------------
extern "C" void kernel_launch(void* const* d_in, const int* in_sizes, int n_in,
                              void* d_out, int out_size)
{
    const float* x  = (const float*)d_in[0];
    const float* Wq = (const float*)d_in[1];
    const float* bq = (const float*)d_in[2];
    const float* Wk = (const float*)d_in[3];
    const float* bk = (const float*)d_in[4];
    const float* Wv = (const float*)d_in[5];
    const float* bv = (const float*)d_in[6];
    const float* Wo = (const float*)d_in[7];
    const float* bo = (const float*)d_in[8];
    float* out = (float*)d_out;
    (void)in_sizes; (void)n_in; (void)out_size;

    __half *qkv, *xf, *gy, *wqkv, *wo;
    cudaGetSymbolAddress((void**)&qkv, g_qkv);
    cudaGetSymbolAddress((void**)&xf, g_xf);
    cudaGetSymbolAddress((void**)&gy, g_y);
    cudaGetSymbolAddress((void**)&wqkv, g_wqkv);
    cudaGetSymbolAddress((void**)&wo, g_wo);

    cudaFuncSetAttribute(gemm_f16<float>,  cudaFuncAttributeMaxDynamicSharedMemorySize, GSMEM);
    cudaFuncSetAttribute(gemm_f16<__half>, cudaFuncAttributeMaxDynamicSharedMemorySize, GSMEM);

    // 1) fused fp32 -> fp16 conversions (R8 layout)
    conv_all<<<(S_ALL + 255) / 256, 256>>>(x, Wq, Wk, Wv, Wo, xf, wqkv, wo);

    // 2) fused QKV projection (N = 6144), bias segment-selected per CTA
    gemm_f16<__half><<<dim3(NQKV / 128, NTOK / 128), 128, GSMEM>>>(
        xf, wqkv, bq, bk, bv, QCOLS, QCOLS + EDIM, qkv, NQKV, EDIM);

    // 3) per-token attention -> y fp16 ((B,H,S,D) flat == (B,S,E) flat)
    attn_kernel<<<NTOK, 256>>>(qkv, gy);

    // 4) output projection (fp32 out)
    gemm_f16<float><<<dim3(EDIM / 128, NTOK / 128), 128, GSMEM>>>(
        gy, wo, bo, bo, bo, 1 << 30, 1 << 30, out, EDIM, EDIM);
}